// round 1
// baseline (speedup 1.0000x reference)
#include <cuda_runtime.h>
#include <math.h>

// Problem constants (fixed by reference setup: B=8, D=64, H=W=256, R=3)
#define Dd 64
#define Hh 256
#define Ww 256
#define IMG (Hh*Ww)          // 65536
#define Rr 3
#define Kk 49
#define TILE_W 32
#define TILE_H 16
#define HALO_W (TILE_W + 2*Rr)   // 38
#define HALO_H (TILE_H + 2*Rr)   // 22
#define HALO_N (HALO_W*HALO_H)   // 836
#define DC 16                    // channel chunk
#define NCHUNK (Dd/DC)           // 4
#define NTHREADS 256

// Scratch for the global branch (small; device globals per harness rules)
__device__ float g_sums[64*Kk];
__device__ float g_dyg[64];
__device__ float g_dxg[64];

// ---------------------------------------------------------------------------
// Per-pixel softargmax epilogue (49 logits already in registers)
// ---------------------------------------------------------------------------
__device__ __forceinline__ void softargmax_px(const float (&a)[Kk], float invtau,
                                              size_t o, float* __restrict__ out_dy,
                                              float* __restrict__ out_dx,
                                              float* __restrict__ out_cl,
                                              float* __restrict__ out_lw) {
    float m = -1e30f;
#pragma unroll
    for (int k = 0; k < Kk; ++k) m = fmaxf(m, a[k]);
    float s = 0.f, sy = 0.f, sx = 0.f;
#pragma unroll
    for (int k = 0; k < Kk; ++k) {
        float e = __expf((a[k] - m) * invtau);
        s += e;
        sy = fmaf(e, (float)(k / 7 - 3), sy);
        sx = fmaf(e, (float)(k % 7 - 3), sx);
    }
    float inv_s = 1.0f / s;
    float conf = inv_s;                 // max prob = exp(0)/s
    const float u = 1.0f / 49.0f;
    float lw = fminf(fmaxf((conf - u) * (1.0f / (1.0f - u)), 0.f), 1.f);
    out_dy[o] = sy * inv_s;             // dy_local (blended later)
    out_dx[o] = sx * inv_s;             // dx_local (blended later)
    out_cl[o] = conf;
    out_lw[o] = lw;
}

// ---------------------------------------------------------------------------
// Kernel 1: fused normalize + 49-tap correlation + local softargmax + logits
// One CTA = 32x16 pixel tile, 256 threads, 2 x-adjacent pixels per thread.
// Raw dots accumulated in registers; normalization applied as a final scalar
// scale: logit_k = raw_k * (scale/|r|) * (1/|v_tap|).
// ---------------------------------------------------------------------------
__global__ __launch_bounds__(NTHREADS, 1)
void corr_kernel(const float* __restrict__ rubin, const float* __restrict__ vis,
                 const float* __restrict__ ltp, float* __restrict__ out, int B) {
    extern __shared__ float sm[];
    float* s_vis = sm;                               // DC * 836
    float* s_rub = sm + DC * HALO_N;                 // DC * 512
    float* s_nv  = s_rub + DC * (TILE_W * TILE_H);   // 836 (vis norm^2 -> inv-norm)

    const int tid = threadIdx.x;
    const int tx = tid & 15, ty = tid >> 4;
    const int b  = blockIdx.z;
    const int x0 = blockIdx.x * TILE_W;
    const int y0 = blockIdx.y * TILE_H;
    const int lx = tx * 2, ly = ty;
    const int gx = x0 + lx, gy = y0 + ly;

    for (int p = tid; p < HALO_N; p += NTHREADS) s_nv[p] = 0.f;

    float acc0[Kk], acc1[Kk];
#pragma unroll
    for (int k = 0; k < Kk; ++k) { acc0[k] = 0.f; acc1[k] = 0.f; }
    float rn0 = 0.f, rn1 = 0.f;

    const float* rub_b = rubin + (size_t)b * Dd * IMG;
    const float* vis_b = vis   + (size_t)b * Dd * IMG;

    for (int c = 0; c < NCHUNK; ++c) {
        const int d0 = c * DC;
        // Load vis halo chunk (edge-clamped)
        for (int i = tid; i < DC * HALO_N; i += NTHREADS) {
            int d = i / HALO_N, p = i - d * HALO_N;
            int hy = p / HALO_W, hx = p - hy * HALO_W;
            int sy = min(max(y0 - Rr + hy, 0), Hh - 1);
            int sx = min(max(x0 - Rr + hx, 0), Ww - 1);
            s_vis[i] = vis_b[(size_t)(d0 + d) * IMG + sy * Ww + sx];
        }
        // Load rubin tile chunk
        for (int i = tid; i < DC * (TILE_W * TILE_H); i += NTHREADS) {
            int d = i >> 9, p = i & 511;
            int sy = y0 + (p >> 5), sx = x0 + (p & 31);
            s_rub[i] = rub_b[(size_t)(d0 + d) * IMG + sy * Ww + sx];
        }
        __syncthreads();

        // Accumulate vis norm^2 (one thread per halo pixel)
        for (int p = tid; p < HALO_N; p += NTHREADS) {
            float a = 0.f;
#pragma unroll
            for (int d = 0; d < DC; ++d) {
                float v = s_vis[d * HALO_N + p];
                a = fmaf(v, v, a);
            }
            s_nv[p] += a;
        }

        // Main correlation loop: 2 pixels/thread, 9-float window per (d,ky)
        const float* vb = s_vis + ly * HALO_W + lx;
        const float* rb = s_rub + ly * TILE_W + lx;
        for (int d = 0; d < DC; ++d) {
            float2 rr = *(const float2*)(rb + d * (TILE_W * TILE_H));
            rn0 = fmaf(rr.x, rr.x, rn0);
            rn1 = fmaf(rr.y, rr.y, rn1);
            const float* vd = vb + d * HALO_N;
#pragma unroll
            for (int kyy = 0; kyy < 7; ++kyy) {
                const float* row = vd + kyy * HALO_W;
                float2 w01 = *(const float2*)(row);
                float2 w23 = *(const float2*)(row + 2);
                float2 w45 = *(const float2*)(row + 4);
                float2 w67 = *(const float2*)(row + 6);
                float w8 = row[8];
                float w[9] = {w01.x, w01.y, w23.x, w23.y, w45.x, w45.y, w67.x, w67.y, w8};
#pragma unroll
                for (int kxx = 0; kxx < 7; ++kxx) {
                    acc0[kyy * 7 + kxx] = fmaf(rr.x, w[kxx],     acc0[kyy * 7 + kxx]);
                    acc1[kyy * 7 + kxx] = fmaf(rr.y, w[kxx + 1], acc1[kyy * 7 + kxx]);
                }
            }
        }
        __syncthreads();
    }

    // Convert norm^2 -> inverse norm (matches max(sqrt(n),1e-6) semantics)
    for (int p = tid; p < HALO_N; p += NTHREADS)
        s_nv[p] = 1.0f / fmaxf(sqrtf(s_nv[p]), 1e-6f);
    __syncthreads();

    const float tau = fmaxf(__expf(*ltp), 1e-3f);
    const float invtau = 1.0f / tau;
    const float scale = 0.125f;   // 1/sqrt(64)
    const float c0 = scale / fmaxf(sqrtf(rn0), 1e-6f);
    const float c1 = scale / fmaxf(sqrtf(rn1), 1e-6f);

    const size_t P = (size_t)B * IMG;
    float* out_dy = out;
    float* out_dx = out + P;
    float* out_cl = out + 2 * P;
    float* out_lw = out + 3 * P + B;
    float* out_lg = out + 4 * P + B;

    const float* invv = s_nv + ly * HALO_W + lx;
    const size_t pix = (size_t)gy * Ww + gx;
#pragma unroll
    for (int k = 0; k < Kk; ++k) {
        int kyy = k / 7, kxx = k % 7;
        float iv0 = invv[kyy * HALO_W + kxx];
        float iv1 = invv[kyy * HALO_W + kxx + 1];
        acc0[k] *= c0 * iv0;
        acc1[k] *= c1 * iv1;
        *(float2*)(out_lg + (size_t)(b * Kk + k) * IMG + pix) = make_float2(acc0[k], acc1[k]);
    }

    const size_t o0 = (size_t)b * IMG + pix;
    softargmax_px(acc0, invtau, o0,     out_dy, out_dx, out_cl, out_lw);
    softargmax_px(acc1, invtau, o0 + 1, out_dy, out_dx, out_cl, out_lw);
}

// ---------------------------------------------------------------------------
// Kernel 2: per-(b,k) plane sums of logits (for the global mean)
// ---------------------------------------------------------------------------
__global__ void sum_kernel(const float* __restrict__ lg) {
    __shared__ float red[256];
    int plane = blockIdx.x;
    const float4* p = (const float4*)(lg + (size_t)plane * IMG);
    float s = 0.f;
    for (int i = threadIdx.x; i < IMG / 4; i += 256) {
        float4 v = p[i];
        s += (v.x + v.y) + (v.z + v.w);
    }
    red[threadIdx.x] = s;
    __syncthreads();
    for (int off = 128; off > 0; off >>= 1) {
        if (threadIdx.x < off) red[threadIdx.x] += red[threadIdx.x + off];
        __syncthreads();
    }
    if (threadIdx.x == 0) g_sums[plane] = red[0];
}

// ---------------------------------------------------------------------------
// Kernel 3: global softargmax per batch (tiny)
// ---------------------------------------------------------------------------
__global__ void global_kernel(const float* __restrict__ ltp, float* __restrict__ out_cg, int B) {
    int b = threadIdx.x;
    if (b >= B) return;
    const float invtau = 1.0f / fmaxf(__expf(*ltp), 1e-3f);
    float l[Kk];
    float m = -1e30f;
#pragma unroll
    for (int k = 0; k < Kk; ++k) {
        l[k] = g_sums[b * Kk + k] * (1.0f / (float)IMG);
        m = fmaxf(m, l[k]);
    }
    float s = 0.f, sy = 0.f, sx = 0.f;
#pragma unroll
    for (int k = 0; k < Kk; ++k) {
        float e = __expf((l[k] - m) * invtau);
        s += e;
        sy = fmaf(e, (float)(k / 7 - 3), sy);
        sx = fmaf(e, (float)(k % 7 - 3), sx);
    }
    out_cg[b] = 1.0f / s;
    g_dyg[b] = sy / s;
    g_dxg[b] = sx / s;
}

// ---------------------------------------------------------------------------
// Kernel 4: blend local & global flow: dy = lw*dy_l + (1-lw)*dy_g
// ---------------------------------------------------------------------------
__global__ void finalize_kernel(float* __restrict__ out, int B) {
    size_t P = (size_t)B * IMG;
    size_t i = (size_t)blockIdx.x * 256 + threadIdx.x;
    if (i >= P) return;
    int b = (int)(i >> 16);
    float lw = out[3 * P + B + i];
    float dyl = out[i];
    float dxl = out[P + i];
    float w2 = 1.0f - lw;
    out[i]     = fmaf(lw, dyl, w2 * g_dyg[b]);
    out[P + i] = fmaf(lw, dxl, w2 * g_dxg[b]);
}

// ---------------------------------------------------------------------------
extern "C" void kernel_launch(void* const* d_in, const int* in_sizes, int n_in,
                              void* d_out, int out_size) {
    const float* rubin = (const float*)d_in[0];
    const float* vis   = (const float*)d_in[1];
    const float* lt    = (const float*)d_in[2];
    float* out = (float*)d_out;

    int B = in_sizes[0] / (Dd * IMG);
    size_t P = (size_t)B * IMG;

    size_t smem = (size_t)(DC * HALO_N + DC * TILE_W * TILE_H + HALO_N) * sizeof(float);
    cudaFuncSetAttribute(corr_kernel, cudaFuncAttributeMaxDynamicSharedMemorySize, (int)smem);

    dim3 grid(Ww / TILE_W, Hh / TILE_H, B);
    corr_kernel<<<grid, NTHREADS, smem>>>(rubin, vis, lt, out, B);

    const float* lg = out + 4 * P + B;
    sum_kernel<<<B * Kk, 256>>>(lg);

    float* out_cg = out + 3 * P;
    global_kernel<<<1, 64>>>(lt, out_cg, B);

    finalize_kernel<<<(int)((P + 255) / 256), 256>>>(out, B);
}